// round 2
// baseline (speedup 1.0000x reference)
#include <cuda_runtime.h>
#include <math.h>

#define N_ROWS 100000
#define HIDDEN 256
#define NCLASS 64
#define TAU_F 1.0f
#define BN_EPS 1e-5f

// ---------------- device scratch (static allocation only) ----------------
__device__ float g_probs[8];
__device__ float g_sum[NCLASS];
__device__ float g_ssq[NCLASS];
__device__ float g_h[(size_t)N_ROWS * HIDDEN];   // PReLU(x), 102.4 MB scratch

struct GemmParams {
    const float* A[8];   // feat0..5, lab0, lab1   [N, d]
    const float* B[8];   // emb0..5, lemb0, lemb1  [d, 256]
    int d[8];
};

// ---------------- kernel 0: gumbel-softmax gate + zero BN stats ----------------
__global__ void probs_kernel(const float* __restrict__ alpha,
                             const float* __restrict__ gumbels,
                             const int* __restrict__ es) {
    int t = threadIdx.x;
    if (t < NCLASS) { g_sum[t] = 0.f; g_ssq[t] = 0.f; }
    if (t == 0) {
        float ws[8];
        float m = -1e30f;
        #pragma unroll
        for (int i = 0; i < 8; i++) { ws[i] = alpha[es[i]]; m = fmaxf(m, ws[i]); }
        float se = 0.f;
        #pragma unroll
        for (int i = 0; i < 8; i++) se += expf(ws[i] - m);
        float lse = m + logf(se);
        float lg[8];
        float m2 = -1e30f;
        #pragma unroll
        for (int i = 0; i < 8; i++) {
            lg[i] = (ws[i] - lse + gumbels[i]) / TAU_F;
            m2 = fmaxf(m2, lg[i]);
        }
        float s2 = 0.f;
        #pragma unroll
        for (int i = 0; i < 8; i++) { lg[i] = expf(lg[i] - m2); s2 += lg[i]; }
        #pragma unroll
        for (int i = 0; i < 8; i++) g_probs[i] = lg[i] / s2;
    }
}

// ---------------- kernel 1: fused segmented GEMM + PReLU -> g_h ----------------
// C-tile 64 rows x 256 cols, 256 threads, micro-tile 4x16 per thread.
__global__ __launch_bounds__(256, 2) void gemm1_kernel(GemmParams p,
                                                       const float* __restrict__ prelu_ptr) {
    __shared__ float As[64][16];
    __shared__ float Bs[16][HIDDEN];

    const int tid = threadIdx.x;
    const int tx = tid & 15;        // col group: cols tx*16 .. +15
    const int ty = tid >> 4;        // row group: rows ty*4 .. +3
    const int ty4 = ty * 4;
    const int tx16 = tx * 16;
    const int row0 = blockIdx.x * 64;

    float acc[4][16];
    #pragma unroll
    for (int i = 0; i < 4; i++)
        #pragma unroll
        for (int j = 0; j < 16; j++) acc[i][j] = 0.f;

    for (int c = 0; c < 8; c++) {
        const float* __restrict__ A = p.A[c];
        const float* __restrict__ B = p.B[c];
        const int d = p.d[c];
        const float pc = g_probs[c];
        for (int k0 = 0; k0 < d; k0 += 16) {
            // load A tile 64x16 (scalar, row-major)
            #pragma unroll
            for (int l = 0; l < 4; l++) {
                int idx = l * 256 + tid;
                int r = idx >> 4, kk = idx & 15;
                int row = row0 + r, k = k0 + kk;
                As[r][kk] = (row < N_ROWS && k < d) ? A[(long)row * d + k] : 0.f;
            }
            // load B tile 16x256 (float4, scaled by prob), coalesced
            #pragma unroll
            for (int l = 0; l < 4; l++) {
                int idx = l * 256 + tid;
                int kk = idx >> 6, n4 = idx & 63;
                int k = k0 + kk;
                float4 v = make_float4(0.f, 0.f, 0.f, 0.f);
                if (k < d) v = *(const float4*)(B + (long)k * HIDDEN + n4 * 4);
                v.x *= pc; v.y *= pc; v.z *= pc; v.w *= pc;
                *(float4*)&Bs[kk][n4 * 4] = v;
            }
            __syncthreads();
            #pragma unroll
            for (int kk = 0; kk < 16; kk++) {
                float a[4];
                #pragma unroll
                for (int i = 0; i < 4; i++) a[i] = As[ty4 + i][kk];  // half-warp broadcast
                float b[16];
                #pragma unroll
                for (int j4 = 0; j4 < 4; j4++) {
                    float4 bv = *(const float4*)&Bs[kk][tx16 + j4 * 4];
                    b[j4 * 4 + 0] = bv.x; b[j4 * 4 + 1] = bv.y;
                    b[j4 * 4 + 2] = bv.z; b[j4 * 4 + 3] = bv.w;
                }
                #pragma unroll
                for (int i = 0; i < 4; i++)
                    #pragma unroll
                    for (int j = 0; j < 16; j++)
                        acc[i][j] = fmaf(a[i], b[j], acc[i][j]);
            }
            __syncthreads();
        }
    }

    // epilogue: PReLU, store h
    const float pa = *prelu_ptr;
    #pragma unroll
    for (int i = 0; i < 4; i++) {
        int row = row0 + ty4 + i;
        if (row < N_ROWS) {
            #pragma unroll
            for (int j4 = 0; j4 < 4; j4++) {
                float4 v;
                float x0 = acc[i][j4 * 4 + 0]; v.x = (x0 >= 0.f) ? x0 : pa * x0;
                float x1 = acc[i][j4 * 4 + 1]; v.y = (x1 >= 0.f) ? x1 : pa * x1;
                float x2 = acc[i][j4 * 4 + 2]; v.z = (x2 >= 0.f) ? x2 : pa * x2;
                float x3 = acc[i][j4 * 4 + 3]; v.w = (x3 >= 0.f) ? x3 : pa * x3;
                *(float4*)&g_h[(long)row * HIDDEN + tx16 + j4 * 4] = v;
            }
        }
    }
}

// ---------------- kernel 2: z = h @ w_out^T + BN partial stats ----------------
// z-tile 64 rows x 64 classes per block, micro 4x4, K=256 in chunks of 16.
__global__ __launch_bounds__(256) void gemm2_kernel(const float* __restrict__ w_out,
                                                    float* __restrict__ z) {
    __shared__ float Hs[64][17];
    __shared__ float Ws[64][17];
    __shared__ float s_sum[NCLASS];
    __shared__ float s_ssq[NCLASS];

    const int tid = threadIdx.x;
    const int tx = tid & 15;       // class group: classes tx*4 .. +3
    const int ty = tid >> 4;       // row group:   rows ty*4 .. +3
    const int row0 = blockIdx.x * 64;

    if (tid < NCLASS) { s_sum[tid] = 0.f; s_ssq[tid] = 0.f; }

    float acc[4][4];
    #pragma unroll
    for (int i = 0; i < 4; i++)
        #pragma unroll
        for (int j = 0; j < 4; j++) acc[i][j] = 0.f;

    for (int k0 = 0; k0 < HIDDEN; k0 += 16) {
        #pragma unroll
        for (int l = 0; l < 4; l++) {
            int idx = l * 256 + tid;
            int r = idx >> 4, kk = idx & 15;
            int row = row0 + r;
            Hs[r][kk] = (row < N_ROWS) ? g_h[(long)row * HIDDEN + k0 + kk] : 0.f;
            Ws[r][kk] = w_out[(long)r * HIDDEN + k0 + kk];  // r = class index here
        }
        __syncthreads();
        #pragma unroll
        for (int kk = 0; kk < 16; kk++) {
            float a[4], w[4];
            #pragma unroll
            for (int i = 0; i < 4; i++) a[i] = Hs[ty * 4 + i][kk];
            #pragma unroll
            for (int j = 0; j < 4; j++) w[j] = Ws[tx * 4 + j][kk];
            #pragma unroll
            for (int i = 0; i < 4; i++)
                #pragma unroll
                for (int j = 0; j < 4; j++)
                    acc[i][j] = fmaf(a[i], w[j], acc[i][j]);
        }
        __syncthreads();
    }

    // write z + accumulate per-class partial sums (valid rows only)
    float s[4] = {0.f, 0.f, 0.f, 0.f};
    float q[4] = {0.f, 0.f, 0.f, 0.f};
    #pragma unroll
    for (int i = 0; i < 4; i++) {
        int row = row0 + ty * 4 + i;
        if (row < N_ROWS) {
            float4 v = make_float4(acc[i][0], acc[i][1], acc[i][2], acc[i][3]);
            *(float4*)&z[(long)row * NCLASS + tx * 4] = v;
            s[0] += v.x; q[0] += v.x * v.x;
            s[1] += v.y; q[1] += v.y * v.y;
            s[2] += v.z; q[2] += v.z * v.z;
            s[3] += v.w; q[3] += v.w * v.w;
        }
    }
    #pragma unroll
    for (int j = 0; j < 4; j++) {
        atomicAdd(&s_sum[tx * 4 + j], s[j]);
        atomicAdd(&s_ssq[tx * 4 + j], q[j]);
    }
    __syncthreads();
    if (tid < NCLASS) {
        atomicAdd(&g_sum[tid], s_sum[tid]);
        atomicAdd(&g_ssq[tid], s_ssq[tid]);
    }
}

// ---------------- kernel 3: batchnorm normalize in place ----------------
__global__ void bn_kernel(float* __restrict__ z) {
    __shared__ float mean_s[NCLASS];
    __shared__ float rstd_s[NCLASS];
    int t = threadIdx.x;
    if (t < NCLASS) {
        float m = g_sum[t] * (1.0f / (float)N_ROWS);
        float v = g_ssq[t] * (1.0f / (float)N_ROWS) - m * m;
        mean_s[t] = m;
        rstd_s[t] = rsqrtf(v + BN_EPS);
    }
    __syncthreads();
    const size_t total = (size_t)N_ROWS * NCLASS;
    for (size_t i = (size_t)blockIdx.x * blockDim.x + t; i < total;
         i += (size_t)gridDim.x * blockDim.x) {
        int c = (int)(i & (NCLASS - 1));
        z[i] = (z[i] - mean_s[c]) * rstd_s[c];
    }
}

// ---------------- host launcher ----------------
extern "C" void kernel_launch(void* const* d_in, const int* in_sizes, int n_in,
                              void* d_out, int out_size) {
    static const long dims[6] = {334, 512, 128, 745, 256, 600};
    const float* feat[8] = {0};
    const float* emb[8]  = {0};
    const float* alpha = 0;
    const float* gumbels = 0;
    const float* prelu_a = 0;
    const float* w_out = 0;
    const int* es = 0;
    int labc = 0, l16 = 0, c8 = 0;

    // Bind inputs by element count (robust to either metadata ordering).
    for (int i = 0; i < n_in; i++) {
        long s = (long)in_sizes[i];
        const void* ptr = d_in[i];
        bool matched = false;
        for (int k = 0; k < 6; k++) {
            if (s == 100000L * dims[k] && !feat[k]) { feat[k] = (const float*)ptr; matched = true; break; }
            if (s == dims[k] * 256L    && !emb[k])  { emb[k]  = (const float*)ptr; matched = true; break; }
        }
        if (matched) continue;
        if (s == 6400000L) {                       // lab0, lab1 (in order)
            if (labc < 2) feat[6 + labc] = (const float*)ptr;
            labc++;
        } else if (s == 16384L) {                  // lemb0, lemb1, w_out (in order)
            if (l16 < 2) emb[6 + l16] = (const float*)ptr;
            else w_out = (const float*)ptr;
            l16++;
        } else if (s == 8L) {                      // alpha, gumbels, epoch_sampled (in order)
            if (c8 == 0) alpha = (const float*)ptr;
            else if (c8 == 1) gumbels = (const float*)ptr;
            else es = (const int*)ptr;
            c8++;
        } else if (s == 1L) {
            prelu_a = (const float*)ptr;
        }
    }

    GemmParams gp;
    for (int c = 0; c < 8; c++) {
        gp.A[c] = feat[c];
        gp.B[c] = emb[c];
        gp.d[c] = (c < 6) ? (int)dims[c] : NCLASS;
    }

    float* z = (float*)d_out;
    const int grid1 = (N_ROWS + 63) / 64;   // 1563

    probs_kernel<<<1, 128>>>(alpha, gumbels, es);
    gemm1_kernel<<<grid1, 256>>>(gp, prelu_a);
    gemm2_kernel<<<grid1, 256>>>(w_out, z);
    bn_kernel<<<1024, 256>>>(z);
}

// round 3
// speedup vs baseline: 6.0371x; 6.0371x over previous
#include <cuda_runtime.h>
#include <math.h>
#include <stdint.h>

#define N_ROWS 100000
#define HIDDEN 256
#define NCLASS 64
#define TAU_F 1.0f
#define BN_EPS 1e-5f

#define BM 128
#define BK 32
#define THREADS 512
#define AS_STRIDE 36
#define BS_STRIDE 264
#define HS_STRIDE 132
#define WS_STRIDE 68

// mainloop smem: As 128*36 + Bs 32*264 floats = 52224 B
// epilogue smem: sh_h 128*132 + sh_w 128*68 floats = 102400 B
#define SMEM_BYTES 102400
#define BS_OFF (BM * AS_STRIDE)          // 4608 floats
#define WS_OFF (BM * HS_STRIDE)          // 16896 floats

// ---------------- device scratch ----------------
__device__ float g_probs[8];
__device__ float g_sum[NCLASS];
__device__ float g_ssq[NCLASS];

struct GemmParams {
    const float* A[8];   // feat0..5, lab0, lab1   [N, d]
    const float* B[8];   // emb0..5, lemb0, lemb1  [d, 256]
    int d[8];
};

__device__ __forceinline__ float f2tf32(float x) {
    uint32_t u;
    asm("cvt.rna.tf32.f32 %0, %1;" : "=r"(u) : "f"(x));
    return __uint_as_float(u);
}

// ---------------- kernel 0: gumbel-softmax gate + zero BN stats ----------------
__global__ void probs_kernel(const float* __restrict__ alpha,
                             const float* __restrict__ gumbels,
                             const int* __restrict__ es) {
    int t = threadIdx.x;
    if (t < NCLASS) { g_sum[t] = 0.f; g_ssq[t] = 0.f; }
    if (t == 0) {
        float ws[8];
        float m = -1e30f;
        #pragma unroll
        for (int i = 0; i < 8; i++) { ws[i] = alpha[es[i]]; m = fmaxf(m, ws[i]); }
        float se = 0.f;
        #pragma unroll
        for (int i = 0; i < 8; i++) se += expf(ws[i] - m);
        float lse = m + logf(se);
        float lg[8];
        float m2 = -1e30f;
        #pragma unroll
        for (int i = 0; i < 8; i++) {
            lg[i] = (ws[i] - lse + gumbels[i]) / TAU_F;
            m2 = fmaxf(m2, lg[i]);
        }
        float s2 = 0.f;
        #pragma unroll
        for (int i = 0; i < 8; i++) { lg[i] = expf(lg[i] - m2); s2 += lg[i]; }
        #pragma unroll
        for (int i = 0; i < 8; i++) g_probs[i] = lg[i] / s2;
    }
}

// ---------------- kernel 1: segmented tf32-MMA GEMM + PReLU + GEMM2 + stats ----
__global__ __launch_bounds__(THREADS, 1)
void gemm1_kernel(GemmParams p, const float* __restrict__ prelu_ptr,
                  const float* __restrict__ w_out, float* __restrict__ z) {
    extern __shared__ float smem[];
    float* As = smem;                 // [128][36]  (tf32 bits)
    float* Bs = smem + BS_OFF;        // [32][264]  (tf32 bits, prob-scaled)
    float* sh_h = smem;               // [128][132] (epilogue, fp32)
    float* sh_w = smem + WS_OFF;      // [128][68]  k-major w_out half

    __shared__ float s_sum[NCLASS];
    __shared__ float s_ssq[NCLASS];

    const int tid = threadIdx.x;
    const int wid = tid >> 5, lane = tid & 31;
    const int wm = wid >> 3, wn = wid & 7;     // warp grid 2 x 8
    const int g = lane >> 2, t4 = lane & 3;
    const int row0 = blockIdx.x * BM;

    if (tid < NCLASS) { s_sum[tid] = 0.f; s_ssq[tid] = 0.f; }

    float acc[4][4][4];
    #pragma unroll
    for (int t = 0; t < 4; t++)
        #pragma unroll
        for (int u = 0; u < 4; u++)
            #pragma unroll
            for (int i = 0; i < 4; i++) acc[t][u][i] = 0.f;

    // prefetch registers
    float  ra[8];
    float4 rb[4];

    auto load_tile = [&](int cs, int k0) {
        const float* __restrict__ A = p.A[cs];
        const float* __restrict__ B = p.B[cs];
        const int d = p.d[cs];
        const float pc = g_probs[cs];
        const int ka = k0 + (tid & 31);
        const int rbase = tid >> 5;
        #pragma unroll
        for (int l = 0; l < 8; l++) {
            int row = row0 + rbase + l * 16;
            ra[l] = (row < N_ROWS && ka < d) ? A[(long)row * d + ka] : 0.f;
        }
        #pragma unroll
        for (int l = 0; l < 4; l++) {
            int flat = l * THREADS + tid;
            int kk = flat >> 6, n4 = flat & 63;
            int k = k0 + kk;
            float4 v = make_float4(0.f, 0.f, 0.f, 0.f);
            if (k < d) v = *(const float4*)(B + (long)k * HIDDEN + n4 * 4);
            v.x *= pc; v.y *= pc; v.z *= pc; v.w *= pc;
            rb[l] = v;
        }
    };

    auto store_tile = [&]() {
        const int rbase = tid >> 5;
        const int ka = tid & 31;
        #pragma unroll
        for (int l = 0; l < 8; l++)
            As[(rbase + l * 16) * AS_STRIDE + ka] = f2tf32(ra[l]);
        #pragma unroll
        for (int l = 0; l < 4; l++) {
            int flat = l * THREADS + tid;
            int kk = flat >> 6, n4 = flat & 63;
            float4 v = rb[l];
            float4 w4 = make_float4(f2tf32(v.x), f2tf32(v.y), f2tf32(v.z), f2tf32(v.w));
            *(float4*)&Bs[kk * BS_STRIDE + n4 * 4] = w4;
        }
    };

    auto compute_chunk = [&]() {
        #pragma unroll
        for (int ks = 0; ks < 4; ks++) {
            const int kk = ks * 8;
            uint32_t a[4][4];
            #pragma unroll
            for (int t = 0; t < 4; t++) {
                int base = (wm * 64 + t * 16 + g) * AS_STRIDE + kk + t4;
                a[t][0] = __float_as_uint(As[base]);
                a[t][1] = __float_as_uint(As[base + 8 * AS_STRIDE]);
                a[t][2] = __float_as_uint(As[base + 4]);
                a[t][3] = __float_as_uint(As[base + 8 * AS_STRIDE + 4]);
            }
            uint32_t b[4][2];
            #pragma unroll
            for (int u = 0; u < 4; u++) {
                int base = (kk + t4) * BS_STRIDE + wn * 32 + u * 8 + g;
                b[u][0] = __float_as_uint(Bs[base]);
                b[u][1] = __float_as_uint(Bs[base + 4 * BS_STRIDE]);
            }
            #pragma unroll
            for (int t = 0; t < 4; t++)
                #pragma unroll
                for (int u = 0; u < 4; u++)
                    asm volatile(
                        "mma.sync.aligned.m16n8k8.row.col.f32.tf32.tf32.f32 "
                        "{%0,%1,%2,%3}, {%4,%5,%6,%7}, {%8,%9}, {%0,%1,%2,%3};\n"
                        : "+f"(acc[t][u][0]), "+f"(acc[t][u][1]),
                          "+f"(acc[t][u][2]), "+f"(acc[t][u][3])
                        : "r"(a[t][0]), "r"(a[t][1]), "r"(a[t][2]), "r"(a[t][3]),
                          "r"(b[u][0]), "r"(b[u][1]));
        }
    };

    // -------- mainloop over 8 segments, K-chunks of 32, reg-prefetch pipeline --
    int cs = 0, ks = 0;
    load_tile(cs, ks);
    for (;;) {
        store_tile();
        __syncthreads();
        ks += BK;
        if (ks >= p.d[cs]) { ks = 0; ++cs; }
        const bool more = (cs < 8);
        if (more) load_tile(cs, ks);
        compute_chunk();
        __syncthreads();
        if (!more) break;
    }

    // -------- epilogue: PReLU + z = h @ w_out^T (two 128-col K halves) --------
    const float pa = *prelu_ptr;
    float accz[4][4];
    #pragma unroll
    for (int i = 0; i < 4; i++)
        #pragma unroll
        for (int j = 0; j < 4; j++) accz[i][j] = 0.f;

    const int rg = tid >> 4;   // 0..31 -> rows rg*4..+3
    const int cg = tid & 15;   // 0..15 -> classes cg*4..+3

    #pragma unroll
    for (int kh = 0; kh < 2; kh++) {
        // warps owning hidden cols [kh*128, kh*128+128) stage PReLU(x) to smem
        if ((wn >> 2) == kh) {
            const int cbase = (wn & 3) * 32;
            #pragma unroll
            for (int t = 0; t < 4; t++) {
                const int r1 = wm * 64 + t * 16 + g;
                #pragma unroll
                for (int u = 0; u < 4; u++) {
                    const int col = cbase + u * 8 + t4 * 2;
                    float x0 = acc[t][u][0], x1 = acc[t][u][1];
                    float x2 = acc[t][u][2], x3 = acc[t][u][3];
                    float2 h01 = make_float2(x0 >= 0.f ? x0 : pa * x0,
                                             x1 >= 0.f ? x1 : pa * x1);
                    float2 h23 = make_float2(x2 >= 0.f ? x2 : pa * x2,
                                             x3 >= 0.f ? x3 : pa * x3);
                    *(float2*)&sh_h[r1 * HS_STRIDE + col] = h01;
                    *(float2*)&sh_h[(r1 + 8) * HS_STRIDE + col] = h23;
                }
            }
        }
        // stage w_out[:, kh*128 : +128] k-major into smem (L1/L2-resident, 64KB)
        #pragma unroll
        for (int l = 0; l < 4; l++) {
            int flat = l * THREADS + tid;
            int c = flat & 63, kq = flat >> 6;
            float4 wv = *(const float4*)(w_out + (long)c * HIDDEN + kh * 128 + kq * 4);
            sh_w[(kq * 4 + 0) * WS_STRIDE + c] = wv.x;
            sh_w[(kq * 4 + 1) * WS_STRIDE + c] = wv.y;
            sh_w[(kq * 4 + 2) * WS_STRIDE + c] = wv.z;
            sh_w[(kq * 4 + 3) * WS_STRIDE + c] = wv.w;
        }
        __syncthreads();
        #pragma unroll 8
        for (int k = 0; k < 128; k++) {
            float a0 = sh_h[(rg * 4 + 0) * HS_STRIDE + k];
            float a1 = sh_h[(rg * 4 + 1) * HS_STRIDE + k];
            float a2 = sh_h[(rg * 4 + 2) * HS_STRIDE + k];
            float a3 = sh_h[(rg * 4 + 3) * HS_STRIDE + k];
            float4 wv = *(float4*)&sh_w[k * WS_STRIDE + cg * 4];
            accz[0][0] = fmaf(a0, wv.x, accz[0][0]);
            accz[0][1] = fmaf(a0, wv.y, accz[0][1]);
            accz[0][2] = fmaf(a0, wv.z, accz[0][2]);
            accz[0][3] = fmaf(a0, wv.w, accz[0][3]);
            accz[1][0] = fmaf(a1, wv.x, accz[1][0]);
            accz[1][1] = fmaf(a1, wv.y, accz[1][1]);
            accz[1][2] = fmaf(a1, wv.z, accz[1][2]);
            accz[1][3] = fmaf(a1, wv.w, accz[1][3]);
            accz[2][0] = fmaf(a2, wv.x, accz[2][0]);
            accz[2][1] = fmaf(a2, wv.y, accz[2][1]);
            accz[2][2] = fmaf(a2, wv.z, accz[2][2]);
            accz[2][3] = fmaf(a2, wv.w, accz[2][3]);
            accz[3][0] = fmaf(a3, wv.x, accz[3][0]);
            accz[3][1] = fmaf(a3, wv.y, accz[3][1]);
            accz[3][2] = fmaf(a3, wv.z, accz[3][2]);
            accz[3][3] = fmaf(a3, wv.w, accz[3][3]);
        }
        __syncthreads();
    }

    // -------- write z + BN partial stats --------
    float s[4] = {0.f, 0.f, 0.f, 0.f};
    float q[4] = {0.f, 0.f, 0.f, 0.f};
    #pragma unroll
    for (int i = 0; i < 4; i++) {
        int row = row0 + rg * 4 + i;
        if (row < N_ROWS) {
            float4 v = make_float4(accz[i][0], accz[i][1], accz[i][2], accz[i][3]);
            *(float4*)&z[(long)row * NCLASS + cg * 4] = v;
            s[0] += v.x; q[0] += v.x * v.x;
            s[1] += v.y; q[1] += v.y * v.y;
            s[2] += v.z; q[2] += v.z * v.z;
            s[3] += v.w; q[3] += v.w * v.w;
        }
    }
    #pragma unroll
    for (int j = 0; j < 4; j++) {
        atomicAdd(&s_sum[cg * 4 + j], s[j]);
        atomicAdd(&s_ssq[cg * 4 + j], q[j]);
    }
    __syncthreads();
    if (tid < NCLASS) {
        atomicAdd(&g_sum[tid], s_sum[tid]);
        atomicAdd(&g_ssq[tid], s_ssq[tid]);
    }
}

// ---------------- kernel 2: batchnorm normalize in place ----------------
__global__ void bn_kernel(float* __restrict__ z) {
    __shared__ float mean_s[NCLASS];
    __shared__ float rstd_s[NCLASS];
    int t = threadIdx.x;
    if (t < NCLASS) {
        float m = g_sum[t] * (1.0f / (float)N_ROWS);
        float v = g_ssq[t] * (1.0f / (float)N_ROWS) - m * m;
        mean_s[t] = m;
        rstd_s[t] = rsqrtf(v + BN_EPS);
    }
    __syncthreads();
    const size_t total = (size_t)N_ROWS * NCLASS;
    for (size_t i = (size_t)blockIdx.x * blockDim.x + t; i < total;
         i += (size_t)gridDim.x * blockDim.x) {
        int c = (int)(i & (NCLASS - 1));
        z[i] = (z[i] - mean_s[c]) * rstd_s[c];
    }
}

// ---------------- host launcher ----------------
extern "C" void kernel_launch(void* const* d_in, const int* in_sizes, int n_in,
                              void* d_out, int out_size) {
    static const long dims[6] = {334, 512, 128, 745, 256, 600};
    const float* feat[8] = {0};
    const float* emb[8]  = {0};
    const float* alpha = 0;
    const float* gumbels = 0;
    const float* prelu_a = 0;
    const float* w_out = 0;
    const int* es = 0;
    int labc = 0, l16 = 0, c8 = 0;

    for (int i = 0; i < n_in; i++) {
        long s = (long)in_sizes[i];
        const void* ptr = d_in[i];
        bool matched = false;
        for (int k = 0; k < 6; k++) {
            if (s == 100000L * dims[k] && !feat[k]) { feat[k] = (const float*)ptr; matched = true; break; }
            if (s == dims[k] * 256L    && !emb[k])  { emb[k]  = (const float*)ptr; matched = true; break; }
        }
        if (matched) continue;
        if (s == 6400000L) {
            if (labc < 2) feat[6 + labc] = (const float*)ptr;
            labc++;
        } else if (s == 16384L) {
            if (l16 < 2) emb[6 + l16] = (const float*)ptr;
            else w_out = (const float*)ptr;
            l16++;
        } else if (s == 8L) {
            if (c8 == 0) alpha = (const float*)ptr;
            else if (c8 == 1) gumbels = (const float*)ptr;
            else es = (const int*)ptr;
            c8++;
        } else if (s == 1L) {
            prelu_a = (const float*)ptr;
        }
    }

    GemmParams gp;
    for (int c = 0; c < 8; c++) {
        gp.A[c] = feat[c];
        gp.B[c] = emb[c];
        gp.d[c] = (c < 6) ? (int)dims[c] : NCLASS;
    }

    float* z = (float*)d_out;
    const int grid1 = (N_ROWS + BM - 1) / BM;   // 782

    static int attr_set = 0;
    if (!attr_set) {
        cudaFuncSetAttribute(gemm1_kernel,
                             cudaFuncAttributeMaxDynamicSharedMemorySize, SMEM_BYTES);
        attr_set = 1;
    }

    probs_kernel<<<1, 128>>>(alpha, gumbels, es);
    gemm1_kernel<<<grid1, THREADS, SMEM_BYTES>>>(gp, prelu_a, w_out, z);
    bn_kernel<<<1024, 256>>>(z);
}